// round 11
// baseline (speedup 1.0000x reference)
#include <cuda_runtime.h>
#include <cuda_bf16.h>
#include <math.h>
#include <float.h>
#include <stdint.h>

#define NB 8
#define NP 1024
#define KNN 20
#define KPMAX 1344   // 3*448 rounded to 64

// ---------------- scratch (device globals; no allocation allowed) ----------------
__device__ __align__(16) float g_dist[NB * NP * NP];            // 32 MB
__device__ __align__(16) int   g_idx[NB * NP * KNN];
__device__ __align__(16) float g_xx[NB * NP];
__device__ __align__(16) float g_cat[NB * NP * 448];
__device__ __align__(16) float g_ab[NB * NP * 1024];
__device__ __align__(16) float g_hf[NB * NP * 512];
__device__ __align__(16) float g_pooled[NB * 512];
__device__ __align__(16) float g_bias4[4 * 512];
__device__ __align__(16) __nv_bfloat16 g_s1[NB * NP * KPMAX];   // [hi|lo|hi]
__device__ __align__(16) __nv_bfloat16 g_s2[NB * NP * KPMAX];   // [hi|hi|lo]
__device__ __align__(16) __nv_bfloat16 g_wabs4[4][1024 * KPMAX]; // per-layer folded weights

// =================== helpers ===================
__device__ __forceinline__ uint32_t smem_u32(const void* p) {
    uint32_t a;
    asm("{ .reg .u64 t; cvta.to.shared.u64 t, %1; cvt.u32.u64 %0, t; }" : "=r"(a) : "l"(p));
    return a;
}
__device__ __forceinline__ void cpa16(uint32_t s, const void* g) {
    asm volatile("cp.async.cg.shared.global [%0], [%1], 16;" :: "r"(s), "l"(g));
}
#define CP_COMMIT() asm volatile("cp.async.commit_group;")
#define CP_WAIT2()  asm volatile("cp.async.wait_group 2;")
#define CP_WAIT1()  asm volatile("cp.async.wait_group 1;")
#define CP_WAIT0()  asm volatile("cp.async.wait_group 0;")

__device__ __forceinline__ void ldsm_x4(uint32_t* r, uint32_t addr) {
    asm volatile("ldmatrix.sync.aligned.m8n8.x4.shared.b16 {%0,%1,%2,%3}, [%4];"
        : "=r"(r[0]), "=r"(r[1]), "=r"(r[2]), "=r"(r[3]) : "r"(addr));
}

// =================== feature split (vectorized) + fused squared norms ===================
__global__ void split_kernel(const float* __restrict__ src, int ld, int coff, int C,
                             long long bstride, int rows_per_b,
                             __nv_bfloat16* __restrict__ s1,
                             __nv_bfloat16* __restrict__ s2, int Kp,
                             float* __restrict__ xxout)
{
    __shared__ float red[4];
    int r = blockIdx.x;
    int b = r / rows_per_b;
    int ri = r - b * rows_per_b;
    const float* p = src + (long long)b * bstride + (long long)ri * ld + coff;
    __nv_bfloat16* o1 = s1 + (long long)r * Kp;
    __nv_bfloat16* o2 = s2 + (long long)r * Kp;
    __nv_bfloat16 z = __float2bfloat16(0.f);
    float ss = 0.f;
    for (int k0 = threadIdx.x * 8; k0 < Kp; k0 += blockDim.x * 8) {
        __nv_bfloat16 v1[8], v2[8];
        #pragma unroll
        for (int j = 0; j < 8; j++) {
            int k = k0 + j;
            __nv_bfloat16 a = z, bb = z;
            if (k < 3 * C) {
                int region = (k < C) ? 0 : ((k < 2 * C) ? 1 : 2);
                int c = k - region * C;
                float x = p[c];
                if (region == 0) ss += x * x;
                __nv_bfloat16 hi = __float2bfloat16(x);
                __nv_bfloat16 lo = __float2bfloat16(x - __bfloat162float(hi));
                a  = (region == 1) ? lo : hi;
                bb = (region == 2) ? lo : hi;
            }
            v1[j] = a; v2[j] = bb;
        }
        *(uint4*)(o1 + k0) = *(uint4*)v1;
        *(uint4*)(o2 + k0) = *(uint4*)v2;
    }
    int lane = threadIdx.x & 31, w = threadIdx.x >> 5;
    #pragma unroll
    for (int o = 16; o; o >>= 1) ss += __shfl_xor_sync(0xffffffffu, ss, o);
    if (!lane) red[w] = ss;
    __syncthreads();
    if (threadIdx.x == 0)
        xxout[r] = red[0] + red[1] + red[2] + red[3];
}

// =================== fold BN into weights + bf16 split, fused ===================
__global__ void wfoldsplit_kernel(const float* __restrict__ W, const float* __restrict__ g,
                                  const float* __restrict__ be, const float* __restrict__ m,
                                  const float* __restrict__ v, int O, int C, int Kp,
                                  __nv_bfloat16* __restrict__ wabs,
                                  float* __restrict__ bias)
{
    int r = blockIdx.x;                 // 0 .. 2O-1
    bool isA = r < O;
    int o = isA ? r : r - O;
    float s = g[o] * rsqrtf(v[o] + 1e-5f);
    if (threadIdx.x == 0 && isA) bias[o] = be[o] - s * m[o];
    __nv_bfloat16* out = wabs + (long long)r * Kp;
    __nv_bfloat16 z = __float2bfloat16(0.f);
    for (int k = threadIdx.x; k < Kp; k += blockDim.x) {
        __nv_bfloat16 vv = z;
        if (k < 3 * C) {
            int region = (k < C) ? 0 : ((k < 2 * C) ? 1 : 2);
            int c = k - region * C;
            float wc = W[o * 2 * C + c];
            float wd = W[o * 2 * C + C + c];
            float val = isA ? s * (wd - wc) : s * wc;
            __nv_bfloat16 hi = __float2bfloat16(val);
            __nv_bfloat16 lo = __float2bfloat16(val - __bfloat162float(hi));
            vv = (region == 2) ? lo : hi;
        }
        out[k] = vv;
    }
}

// =================== mma.sync bf16 GEMM, 3-stage cp.async + ldmatrix ===================
#define SSTR 56
#define ASZ  (128 * SSTR)
#define NSTAGE 3
#define GEMM_SMEM (NSTAGE * ASZ * 2 * 2)

__device__ __forceinline__ void mma16816(float* c, const uint32_t* a, const uint32_t* b)
{
    asm volatile(
        "mma.sync.aligned.m16n8k16.row.col.f32.bf16.bf16.f32 "
        "{%0,%1,%2,%3}, {%4,%5,%6,%7}, {%8,%9}, {%0,%1,%2,%3};"
        : "+f"(c[0]), "+f"(c[1]), "+f"(c[2]), "+f"(c[3])
        : "r"(a[0]), "r"(a[1]), "r"(a[2]), "r"(a[3]), "r"(b[0]), "r"(b[1]));
}

__global__ __launch_bounds__(256, 2) void mma_gemm_kernel(
    const __nv_bfloat16* __restrict__ A,
    const __nv_bfloat16* __restrict__ Bm,
    int Kp, long long bsA, long long bsB,
    const float* __restrict__ xx, int mode,
    float* __restrict__ out, int ldo)
{
    extern __shared__ __align__(16) __nv_bfloat16 sm[];
    __nv_bfloat16* As = sm;
    __nv_bfloat16* Bs = sm + NSTAGE * ASZ;

    int b = blockIdx.z;
    int row0 = blockIdx.y * 128;
    int col0 = blockIdx.x * 128;
    int tid = threadIdx.x;
    int wid = tid >> 5, lane = tid & 31;
    int wm = (wid >> 2) * 64;
    int wn = (wid & 3) * 32;

    const __nv_bfloat16* Ab = A + (long long)b * bsA;
    const __nv_bfloat16* Bb = Bm + (long long)b * bsB;

    int lr = tid >> 1;
    int lc = (tid & 1) * 16;

    uint32_t sAraw = smem_u32(As);
    uint32_t sBraw = smem_u32(Bs);
    uint32_t sA0 = sAraw + (uint32_t)(lr * SSTR + lc) * 2;
    uint32_t sB0 = sBraw + (uint32_t)(lr * SSTR + lc) * 2;
    const __nv_bfloat16* gA = Ab + (long long)(row0 + lr) * Kp + lc;
    const __nv_bfloat16* gB = Bb + (long long)(col0 + lr) * Kp + lc;

    uint32_t a_off = (uint32_t)((wm + (lane & 15)) * SSTR + (lane >> 4) * 8);
    uint32_t b_off = (uint32_t)((wn + (lane & 7) + ((lane >> 4) & 1) * 8) * SSTR
                                + ((lane >> 3) & 1) * 8);

    int nk = Kp >> 5;

    #pragma unroll
    for (int s = 0; s < NSTAGE - 1; s++) {
        if (s < nk) {
            uint32_t da = sA0 + (uint32_t)(s * ASZ) * 2;
            uint32_t db = sB0 + (uint32_t)(s * ASZ) * 2;
            const __nv_bfloat16* ga = gA + s * 32;
            const __nv_bfloat16* gb = gB + s * 32;
            cpa16(da, ga); cpa16(da + 16, ga + 8);
            cpa16(db, gb); cpa16(db + 16, gb + 8);
            CP_COMMIT();
        }
    }

    float acc[4][4][4] = {};

    for (int kc = 0; kc < nk; kc++) {
        int cur = kc % NSTAGE;
        if (kc + 2 < nk) {
            int nxt = (kc + 2) % NSTAGE;
            const __nv_bfloat16* ga = gA + (kc + 2) * 32;
            const __nv_bfloat16* gb = gB + (kc + 2) * 32;
            uint32_t da = sA0 + (uint32_t)(nxt * ASZ) * 2;
            uint32_t db = sB0 + (uint32_t)(nxt * ASZ) * 2;
            cpa16(da, ga); cpa16(da + 16, ga + 8);
            cpa16(db, gb); cpa16(db + 16, gb + 8);
            CP_COMMIT();
            CP_WAIT2();
        } else if (kc + 1 < nk) {
            CP_WAIT1();
        } else {
            CP_WAIT0();
        }
        __syncthreads();

        uint32_t aCur = sAraw + (uint32_t)(cur * ASZ) * 2 + a_off * 2;
        uint32_t bCur = sBraw + (uint32_t)(cur * ASZ) * 2 + b_off * 2;
        #pragma unroll
        for (int kk = 0; kk < 32; kk += 16) {
            uint32_t af[4][4], bq[2][4];
            #pragma unroll
            for (int mf = 0; mf < 4; mf++)
                ldsm_x4(af[mf], aCur + (uint32_t)(mf * 16 * SSTR + kk) * 2);
            #pragma unroll
            for (int nq = 0; nq < 2; nq++)
                ldsm_x4(bq[nq], bCur + (uint32_t)(nq * 16 * SSTR + kk) * 2);
            #pragma unroll
            for (int mf = 0; mf < 4; mf++)
                #pragma unroll
                for (int nf = 0; nf < 4; nf++)
                    mma16816(acc[mf][nf], af[mf], &bq[nf >> 1][(nf & 1) * 2]);
        }
        __syncthreads();
    }

    int ar = lane >> 2, ac = (lane & 3) * 2;
    if (mode == 0) {
        const float* xxb = xx + b * NP;
        #pragma unroll
        for (int mf = 0; mf < 4; mf++) {
            int r0g = row0 + wm + mf * 16 + ar;
            float xi0 = xxb[r0g], xi1 = xxb[r0g + 8];
            #pragma unroll
            for (int nf = 0; nf < 4; nf++) {
                int cg = col0 + wn + nf * 8 + ac;
                float* acc4 = acc[mf][nf];
                float xj0 = xxb[cg], xj1 = xxb[cg + 1];
                float2 v0, v1;
                v0.x = 2.f * acc4[0] - xi0 - xj0;
                v0.y = 2.f * acc4[1] - xi0 - xj1;
                v1.x = 2.f * acc4[2] - xi1 - xj0;
                v1.y = 2.f * acc4[3] - xi1 - xj1;
                *(float2*)(out + ((long long)b * NP + r0g) * ldo + cg) = v0;
                *(float2*)(out + ((long long)b * NP + r0g + 8) * ldo + cg) = v1;
            }
        }
    } else {
        #pragma unroll
        for (int mf = 0; mf < 4; mf++) {
            int r0g = row0 + wm + mf * 16 + ar;
            #pragma unroll
            for (int nf = 0; nf < 4; nf++) {
                int cg = col0 + wn + nf * 8 + ac;
                float* acc4 = acc[mf][nf];
                float2 v0, v1;
                v0.x = acc4[0]; v0.y = acc4[1];
                v1.x = acc4[2]; v1.y = acc4[3];
                *(float2*)(out + ((long long)b * NP + r0g) * ldo + cg) = v0;
                *(float2*)(out + ((long long)b * NP + r0g + 8) * ldo + cg) = v1;
            }
        }
    }
}

// =================== top-20: vectorized loads + sorted top-4 queues + verify ===================
// slot s of lane l holds element l*32 + s  (row-major per lane; loaded as 8x LDG.128)
__global__ void topk_kernel(const float* __restrict__ dist, int* __restrict__ idx)
{
    int row = blockIdx.x * (blockDim.x >> 5) + (threadIdx.x >> 5);
    int lane = threadIdx.x & 31;
    if (row >= NB * NP) return;
    const float4* d4 = (const float4*)(dist + (size_t)row * NP);
    float v[32];
    #pragma unroll
    for (int s4 = 0; s4 < 8; s4++) {
        float4 t = d4[lane * 8 + s4];
        v[4 * s4 + 0] = t.x; v[4 * s4 + 1] = t.y;
        v[4 * s4 + 2] = t.z; v[4 * s4 + 3] = t.w;
    }

    float m0 = -FLT_MAX, m1 = -FLT_MAX, m2 = -FLT_MAX, m3 = -FLT_MAX;
    int q0 = 0, q1 = 0, q2 = 0, q3 = 0;
    #pragma unroll
    for (int s = 0; s < 32; s++) {
        float x = v[s];
        if (x > m3) {
            if (x > m0)      { m3 = m2; q3 = q2; m2 = m1; q2 = q1; m1 = m0; q1 = q0; m0 = x; q0 = s; }
            else if (x > m1) { m3 = m2; q3 = q2; m2 = m1; q2 = q1; m1 = x;  q1 = s; }
            else if (x > m2) { m3 = m2; q3 = q2; m2 = x;  q2 = s; }
            else             { m3 = x;  q3 = s; }
        }
    }

    float thresh = 0.f;
    #pragma unroll
    for (int t = 0; t < KNN; t++) {
        float best = m0;
        #pragma unroll
        for (int off = 16; off; off >>= 1)
            best = fmaxf(best, __shfl_xor_sync(0xffffffffu, best, off));
        unsigned mask = __ballot_sync(0xffffffffu, m0 == best);
        int wl = __ffs(mask) - 1;
        int wq = __shfl_sync(0xffffffffu, q0, wl);
        if (lane == 0) idx[row * KNN + t] = wl * 32 + wq;
        if (lane == wl) { m0 = m1; q0 = q1; m1 = m2; q1 = q2; m2 = m3; q2 = q3; m3 = -FLT_MAX; }
        thresh = best;
    }

    int cnt = 0;
    #pragma unroll
    for (int s = 0; s < 32; s++) cnt += (v[s] > thresh) ? 1 : 0;
    cnt = __reduce_add_sync(0xffffffffu, cnt);
    if (cnt == 19) return;

    // rare fallback: exact iterative selection (element = lane*32 + slot)
    for (int t = 0; t < KNN; t++) {
        float best = -FLT_MAX; int bs = 0;
        #pragma unroll
        for (int s = 0; s < 32; s++)
            if (v[s] > best) { best = v[s]; bs = s; }
        int bj = lane * 32 + bs;
        #pragma unroll
        for (int off = 16; off; off >>= 1) {
            float ov = __shfl_xor_sync(0xffffffffu, best, off);
            int oj = __shfl_xor_sync(0xffffffffu, bj, off);
            if (ov > best || (ov == best && oj < bj)) { best = ov; bj = oj; }
        }
        if (lane == 0) idx[row * KNN + t] = bj;
        if ((bj >> 5) == lane) {
            int ks = bj & 31;
            #pragma unroll
            for (int s = 0; s < 32; s++)
                if (s == ks) v[s] = -FLT_MAX;
        }
    }
}

// =================== edge aggregate (float4) ===================
__global__ void aggregate_kernel(const float* __restrict__ ab, int O,
                                 const float* __restrict__ bias,
                                 const int* __restrict__ idx,
                                 float* __restrict__ out, int ldo, int ooff)
{
    int bi = blockIdx.x;
    int b = bi >> 10, i = bi & 1023;
    __shared__ int sj[KNN];
    if (threadIdx.x < KNN) sj[threadIdx.x] = idx[bi * KNN + threadIdx.x];
    __syncthreads();
    const float* abb = ab + (size_t)b * NP * 2 * O;
    int nch = O >> 2;
    for (int t = threadIdx.x; t < nch; t += blockDim.x) {
        float4 a4 = *(const float4*)(abb + (size_t)i * 2 * O + t * 4);
        float4 bi4 = *(const float4*)(bias + t * 4);
        a4.x += bi4.x; a4.y += bi4.y; a4.z += bi4.z; a4.w += bi4.w;
        float4 acc = {0.f, 0.f, 0.f, 0.f};
        #pragma unroll
        for (int k = 0; k < KNN; k++) {
            float4 b4 = *(const float4*)(abb + (size_t)sj[k] * 2 * O + O + t * 4);
            float vx = a4.x + b4.x; acc.x += fmaxf(vx, 0.2f * vx);
            float vy = a4.y + b4.y; acc.y += fmaxf(vy, 0.2f * vy);
            float vz = a4.z + b4.z; acc.z += fmaxf(vz, 0.2f * vz);
            float vw = a4.w + b4.w; acc.w += fmaxf(vw, 0.2f * vw);
        }
        acc.x *= 0.05f; acc.y *= 0.05f; acc.z *= 0.05f; acc.w *= 0.05f;
        *(float4*)(out + ((size_t)b * NP + i) * ldo + ooff + t * 4) = acc;
    }
}

// =================== pooling + final linear ===================
__global__ void pool_kernel(const float* __restrict__ hf, float* __restrict__ pooled)
{
    int b = blockIdx.x;
    int t = threadIdx.x;                 // 128 threads, each owns 4 channels
    float4 s = {0.f, 0.f, 0.f, 0.f};
    const float* base = hf + (size_t)b * NP * 512 + t * 4;
    for (int i = 0; i < NP; i++) {
        float4 x = *(const float4*)(base + (size_t)i * 512);
        s.x += x.x; s.y += x.y; s.z += x.z; s.w += x.w;
    }
    s.x *= (1.f / NP); s.y *= (1.f / NP); s.z *= (1.f / NP); s.w *= (1.f / NP);
    *(float4*)(pooled + b * 512 + t * 4) = s;
}

__global__ void final_kernel(const float* __restrict__ pooled, const float* __restrict__ We,
                             float* __restrict__ out)
{
    int b = blockIdx.x, e = threadIdx.x;
    const float* p = pooled + b * 512;
    const float* w = We + e * 512;
    float s = 0.f;
    for (int o = 0; o < 512; o++) s += p[o] * w[o];
    out[b * 256 + e] = s;
}

// =================== host side ===================
struct LayerCfg { int C, O, coff; const float *W, *g, *be, *m, *v; };

extern "C" void kernel_launch(void* const* d_in, const int* in_sizes, int n_in,
                              void* d_out, int out_size)
{
    const float* x  = (const float*)d_in[0];
    const float* We = (const float*)d_in[21];

    float *dist, *xx, *cat, *ab, *hf, *pooled, *bias4;
    int* idx;
    __nv_bfloat16 *s1, *s2, *wabs4;
    cudaGetSymbolAddress((void**)&dist,   g_dist);
    cudaGetSymbolAddress((void**)&idx,    g_idx);
    cudaGetSymbolAddress((void**)&xx,     g_xx);
    cudaGetSymbolAddress((void**)&cat,    g_cat);
    cudaGetSymbolAddress((void**)&ab,     g_ab);
    cudaGetSymbolAddress((void**)&hf,     g_hf);
    cudaGetSymbolAddress((void**)&pooled, g_pooled);
    cudaGetSymbolAddress((void**)&bias4,  g_bias4);
    cudaGetSymbolAddress((void**)&s1,     g_s1);
    cudaGetSymbolAddress((void**)&s2,     g_s2);
    cudaGetSymbolAddress((void**)&wabs4,  g_wabs4);

    static cudaStream_t sB = nullptr;
    static cudaEvent_t evRoot, evS[4], evB[4];
    static bool attrSet = false;
    if (!sB) {
        cudaStreamCreateWithFlags(&sB, cudaStreamNonBlocking);
        cudaEventCreateWithFlags(&evRoot, cudaEventDisableTiming);
        for (int i = 0; i < 4; i++) {
            cudaEventCreateWithFlags(&evS[i], cudaEventDisableTiming);
            cudaEventCreateWithFlags(&evB[i], cudaEventDisableTiming);
        }
    }
    if (!attrSet) {
        cudaFuncSetAttribute(mma_gemm_kernel,
                             cudaFuncAttributeMaxDynamicSharedMemorySize, GEMM_SMEM);
        attrSet = true;
    }

    LayerCfg L[4] = {
        {  3,  64,   0, (const float*)d_in[1],  (const float*)d_in[2],  (const float*)d_in[3],  (const float*)d_in[4],  (const float*)d_in[5]  },
        { 64, 128,   0, (const float*)d_in[6],  (const float*)d_in[7],  (const float*)d_in[8],  (const float*)d_in[9],  (const float*)d_in[10] },
        {128, 256,  64, (const float*)d_in[11], (const float*)d_in[12], (const float*)d_in[13], (const float*)d_in[14], (const float*)d_in[15] },
        {448, 512,   0, (const float*)d_in[16], (const float*)d_in[17], (const float*)d_in[18], (const float*)d_in[19], (const float*)d_in[20] },
    };
    int ooffs[4] = {0, 64, 192, 0};

    cudaEventRecord(evRoot, 0);
    cudaStreamWaitEvent(sB, evRoot, 0);

    for (int i = 0; i < 4; i++) {
        int Kp = ((3 * L[i].C + 63) / 64) * 64;
        wfoldsplit_kernel<<<2 * L[i].O, 128, 0, sB>>>(
            L[i].W, L[i].g, L[i].be, L[i].m, L[i].v, L[i].O, L[i].C, Kp,
            wabs4 + (size_t)i * 1024 * KPMAX, bias4 + i * 512);
    }

    for (int i = 0; i < 4; i++) {
        int C = L[i].C, O = L[i].O, coff = L[i].coff;
        int Kp = ((3 * C + 63) / 64) * 64;
        const float* hin = (i == 0) ? x : cat;
        int ld = (i == 0) ? 3 : 448;
        float* outbuf = (i == 3) ? hf : cat;
        int ldo = (i == 3) ? 512 : 448;

        split_kernel<<<NB * NP, 128>>>(hin, ld, coff, C, (long long)NP * ld, NP,
                                       s1, s2, Kp, xx);
        cudaEventRecord(evS[i], 0);

        cudaStreamWaitEvent(sB, evS[i], 0);
        dim3 gw((2 * O) / 128, NP / 128, NB);
        mma_gemm_kernel<<<gw, 256, GEMM_SMEM, sB>>>(
            s1, wabs4 + (size_t)i * 1024 * KPMAX, Kp,
            (long long)NP * Kp, 0, nullptr, 1, ab, 2 * O);
        cudaEventRecord(evB[i], sB);

        dim3 gd(NP / 128, NP / 128, NB);
        mma_gemm_kernel<<<gd, 256, GEMM_SMEM>>>(
            s1, s2, Kp, (long long)NP * Kp, (long long)NP * Kp,
            xx, 0, dist, NP);
        topk_kernel<<<NB * NP / 8, 256>>>(dist, idx);

        cudaStreamWaitEvent(0, evB[i], 0);
        int bt = (O >> 2) < 128 ? (O >> 2) : 128;
        if (bt < 32) bt = 32;
        aggregate_kernel<<<NB * NP, bt>>>(ab, O, bias4 + i * 512, idx,
                                          outbuf, ldo, ooffs[i]);
    }

    pool_kernel<<<NB, 128>>>(hf, pooled);
    final_kernel<<<NB, 256>>>(pooled, We, (float*)d_out);
}

// round 12
// speedup vs baseline: 1.0158x; 1.0158x over previous
#include <cuda_runtime.h>
#include <cuda_bf16.h>
#include <math.h>
#include <float.h>
#include <stdint.h>

#define NB 8
#define NP 1024
#define KNN 20
#define KPMAX 1344   // 3*448 rounded to 64

// ---------------- scratch (device globals; no allocation allowed) ----------------
__device__ __align__(16) float g_dist[NB * NP * NP];            // 32 MB
__device__ __align__(16) int   g_idx[NB * NP * KNN];
__device__ __align__(16) float g_xx[NB * NP];
__device__ __align__(16) float g_cat[NB * NP * 448];
__device__ __align__(16) float g_ab[NB * NP * 1024];
__device__ __align__(16) float g_hf[NB * NP * 512];
__device__ __align__(16) float g_pooled[NB * 512];
__device__ __align__(16) float g_bias4[4 * 512];
__device__ __align__(16) __nv_bfloat16 g_s1[NB * NP * KPMAX];   // [hi|lo|hi]
__device__ __align__(16) __nv_bfloat16 g_s2[NB * NP * KPMAX];   // [hi|hi|lo]
__device__ __align__(16) __nv_bfloat16 g_wabs4[4][1024 * KPMAX]; // per-layer folded weights

// =================== helpers ===================
__device__ __forceinline__ uint32_t smem_u32(const void* p) {
    uint32_t a;
    asm("{ .reg .u64 t; cvta.to.shared.u64 t, %1; cvt.u32.u64 %0, t; }" : "=r"(a) : "l"(p));
    return a;
}
__device__ __forceinline__ void cpa16(uint32_t s, const void* g) {
    asm volatile("cp.async.cg.shared.global [%0], [%1], 16;" :: "r"(s), "l"(g));
}
#define CP_COMMIT() asm volatile("cp.async.commit_group;")
#define CP_WAIT2()  asm volatile("cp.async.wait_group 2;")
#define CP_WAIT1()  asm volatile("cp.async.wait_group 1;")
#define CP_WAIT0()  asm volatile("cp.async.wait_group 0;")

__device__ __forceinline__ void ldsm_x4(uint32_t* r, uint32_t addr) {
    asm volatile("ldmatrix.sync.aligned.m8n8.x4.shared.b16 {%0,%1,%2,%3}, [%4];"
        : "=r"(r[0]), "=r"(r[1]), "=r"(r[2]), "=r"(r[3]) : "r"(addr));
}

// =================== feature split (coalesced scalar, R10-proven) + norms ===================
__global__ void split_kernel(const float* __restrict__ src, int ld, int coff, int C,
                             long long bstride, int rows_per_b,
                             __nv_bfloat16* __restrict__ s1,
                             __nv_bfloat16* __restrict__ s2, int Kp,
                             float* __restrict__ xxout)
{
    __shared__ float red[4];
    int r = blockIdx.x;
    int b = r / rows_per_b;
    int ri = r - b * rows_per_b;
    const float* p = src + (long long)b * bstride + (long long)ri * ld + coff;
    __nv_bfloat16* o1 = s1 + (long long)r * Kp;
    __nv_bfloat16* o2 = s2 + (long long)r * Kp;
    __nv_bfloat16 z = __float2bfloat16(0.f);
    float ss = 0.f;
    for (int k = threadIdx.x; k < Kp; k += blockDim.x) {
        __nv_bfloat16 v1 = z, v2 = z;
        if (k < 3 * C) {
            int region = (k < C) ? 0 : ((k < 2 * C) ? 1 : 2);
            int c = k - region * C;
            float x = p[c];
            if (region == 0) ss += x * x;
            __nv_bfloat16 hi = __float2bfloat16(x);
            __nv_bfloat16 lo = __float2bfloat16(x - __bfloat162float(hi));
            v1 = (region == 1) ? lo : hi;
            v2 = (region == 2) ? lo : hi;
        }
        o1[k] = v1;
        o2[k] = v2;
    }
    int lane = threadIdx.x & 31, w = threadIdx.x >> 5;
    #pragma unroll
    for (int o = 16; o; o >>= 1) ss += __shfl_xor_sync(0xffffffffu, ss, o);
    if (!lane) red[w] = ss;
    __syncthreads();
    if (threadIdx.x == 0)
        xxout[r] = red[0] + red[1] + red[2] + red[3];
}

// =================== fold BN into weights + bf16 split, fused ===================
__global__ void wfoldsplit_kernel(const float* __restrict__ W, const float* __restrict__ g,
                                  const float* __restrict__ be, const float* __restrict__ m,
                                  const float* __restrict__ v, int O, int C, int Kp,
                                  __nv_bfloat16* __restrict__ wabs,
                                  float* __restrict__ bias)
{
    int r = blockIdx.x;                 // 0 .. 2O-1
    bool isA = r < O;
    int o = isA ? r : r - O;
    float s = g[o] * rsqrtf(v[o] + 1e-5f);
    if (threadIdx.x == 0 && isA) bias[o] = be[o] - s * m[o];
    __nv_bfloat16* out = wabs + (long long)r * Kp;
    __nv_bfloat16 z = __float2bfloat16(0.f);
    for (int k = threadIdx.x; k < Kp; k += blockDim.x) {
        __nv_bfloat16 vv = z;
        if (k < 3 * C) {
            int region = (k < C) ? 0 : ((k < 2 * C) ? 1 : 2);
            int c = k - region * C;
            float wc = W[o * 2 * C + c];
            float wd = W[o * 2 * C + C + c];
            float val = isA ? s * (wd - wc) : s * wc;
            __nv_bfloat16 hi = __float2bfloat16(val);
            __nv_bfloat16 lo = __float2bfloat16(val - __bfloat162float(hi));
            vv = (region == 2) ? lo : hi;
        }
        out[k] = vv;
    }
}

// =================== mma.sync bf16 GEMM, 3-stage cp.async + ldmatrix ===================
#define SSTR 56
#define ASZ  (128 * SSTR)
#define NSTAGE 3
#define GEMM_SMEM (NSTAGE * ASZ * 2 * 2)

__device__ __forceinline__ void mma16816(float* c, const uint32_t* a, const uint32_t* b)
{
    asm volatile(
        "mma.sync.aligned.m16n8k16.row.col.f32.bf16.bf16.f32 "
        "{%0,%1,%2,%3}, {%4,%5,%6,%7}, {%8,%9}, {%0,%1,%2,%3};"
        : "+f"(c[0]), "+f"(c[1]), "+f"(c[2]), "+f"(c[3])
        : "r"(a[0]), "r"(a[1]), "r"(a[2]), "r"(a[3]), "r"(b[0]), "r"(b[1]));
}

__global__ __launch_bounds__(256, 2) void mma_gemm_kernel(
    const __nv_bfloat16* __restrict__ A,
    const __nv_bfloat16* __restrict__ Bm,
    int Kp, long long bsA, long long bsB,
    const float* __restrict__ xx, int mode,
    float* __restrict__ out, int ldo)
{
    extern __shared__ __align__(16) __nv_bfloat16 sm[];
    __nv_bfloat16* As = sm;
    __nv_bfloat16* Bs = sm + NSTAGE * ASZ;

    int b = blockIdx.z;
    int row0 = blockIdx.y * 128;
    int col0 = blockIdx.x * 128;
    int tid = threadIdx.x;
    int wid = tid >> 5, lane = tid & 31;
    int wm = (wid >> 2) * 64;
    int wn = (wid & 3) * 32;

    const __nv_bfloat16* Ab = A + (long long)b * bsA;
    const __nv_bfloat16* Bb = Bm + (long long)b * bsB;

    int lr = tid >> 1;
    int lc = (tid & 1) * 16;

    uint32_t sAraw = smem_u32(As);
    uint32_t sBraw = smem_u32(Bs);
    uint32_t sA0 = sAraw + (uint32_t)(lr * SSTR + lc) * 2;
    uint32_t sB0 = sBraw + (uint32_t)(lr * SSTR + lc) * 2;
    const __nv_bfloat16* gA = Ab + (long long)(row0 + lr) * Kp + lc;
    const __nv_bfloat16* gB = Bb + (long long)(col0 + lr) * Kp + lc;

    uint32_t a_off = (uint32_t)((wm + (lane & 15)) * SSTR + (lane >> 4) * 8);
    uint32_t b_off = (uint32_t)((wn + (lane & 7) + ((lane >> 4) & 1) * 8) * SSTR
                                + ((lane >> 3) & 1) * 8);

    int nk = Kp >> 5;

    #pragma unroll
    for (int s = 0; s < NSTAGE - 1; s++) {
        if (s < nk) {
            uint32_t da = sA0 + (uint32_t)(s * ASZ) * 2;
            uint32_t db = sB0 + (uint32_t)(s * ASZ) * 2;
            const __nv_bfloat16* ga = gA + s * 32;
            const __nv_bfloat16* gb = gB + s * 32;
            cpa16(da, ga); cpa16(da + 16, ga + 8);
            cpa16(db, gb); cpa16(db + 16, gb + 8);
            CP_COMMIT();
        }
    }

    float acc[4][4][4] = {};

    for (int kc = 0; kc < nk; kc++) {
        int cur = kc % NSTAGE;
        if (kc + 2 < nk) {
            int nxt = (kc + 2) % NSTAGE;
            const __nv_bfloat16* ga = gA + (kc + 2) * 32;
            const __nv_bfloat16* gb = gB + (kc + 2) * 32;
            uint32_t da = sA0 + (uint32_t)(nxt * ASZ) * 2;
            uint32_t db = sB0 + (uint32_t)(nxt * ASZ) * 2;
            cpa16(da, ga); cpa16(da + 16, ga + 8);
            cpa16(db, gb); cpa16(db + 16, gb + 8);
            CP_COMMIT();
            CP_WAIT2();
        } else if (kc + 1 < nk) {
            CP_WAIT1();
        } else {
            CP_WAIT0();
        }
        __syncthreads();

        uint32_t aCur = sAraw + (uint32_t)(cur * ASZ) * 2 + a_off * 2;
        uint32_t bCur = sBraw + (uint32_t)(cur * ASZ) * 2 + b_off * 2;
        #pragma unroll
        for (int kk = 0; kk < 32; kk += 16) {
            uint32_t af[4][4], bq[2][4];
            #pragma unroll
            for (int mf = 0; mf < 4; mf++)
                ldsm_x4(af[mf], aCur + (uint32_t)(mf * 16 * SSTR + kk) * 2);
            #pragma unroll
            for (int nq = 0; nq < 2; nq++)
                ldsm_x4(bq[nq], bCur + (uint32_t)(nq * 16 * SSTR + kk) * 2);
            #pragma unroll
            for (int mf = 0; mf < 4; mf++)
                #pragma unroll
                for (int nf = 0; nf < 4; nf++)
                    mma16816(acc[mf][nf], af[mf], &bq[nf >> 1][(nf & 1) * 2]);
        }
        __syncthreads();
    }

    int ar = lane >> 2, ac = (lane & 3) * 2;
    if (mode == 0) {
        const float* xxb = xx + b * NP;
        #pragma unroll
        for (int mf = 0; mf < 4; mf++) {
            int r0g = row0 + wm + mf * 16 + ar;
            float xi0 = xxb[r0g], xi1 = xxb[r0g + 8];
            #pragma unroll
            for (int nf = 0; nf < 4; nf++) {
                int cg = col0 + wn + nf * 8 + ac;
                float* acc4 = acc[mf][nf];
                float xj0 = xxb[cg], xj1 = xxb[cg + 1];
                float2 v0, v1;
                v0.x = 2.f * acc4[0] - xi0 - xj0;
                v0.y = 2.f * acc4[1] - xi0 - xj1;
                v1.x = 2.f * acc4[2] - xi1 - xj0;
                v1.y = 2.f * acc4[3] - xi1 - xj1;
                *(float2*)(out + ((long long)b * NP + r0g) * ldo + cg) = v0;
                *(float2*)(out + ((long long)b * NP + r0g + 8) * ldo + cg) = v1;
            }
        }
    } else {
        #pragma unroll
        for (int mf = 0; mf < 4; mf++) {
            int r0g = row0 + wm + mf * 16 + ar;
            #pragma unroll
            for (int nf = 0; nf < 4; nf++) {
                int cg = col0 + wn + nf * 8 + ac;
                float* acc4 = acc[mf][nf];
                float2 v0, v1;
                v0.x = acc4[0]; v0.y = acc4[1];
                v1.x = acc4[2]; v1.y = acc4[3];
                *(float2*)(out + ((long long)b * NP + r0g) * ldo + cg) = v0;
                *(float2*)(out + ((long long)b * NP + r0g + 8) * ldo + cg) = v1;
            }
        }
    }
}

// =================== top-20: COALESCED float4 loads + sorted top-4 queues ===================
// slot s (0..31) of lane l holds element (s>>2)*128 + l*4 + (s&3):
//   load step s4 (0..7): lane l reads d4[s4*32 + l] -> consecutive lanes,
//   consecutive 16B (4 lines/request), 8 LDG.128 per thread.
__global__ void topk_kernel(const float* __restrict__ dist, int* __restrict__ idx)
{
    int row = blockIdx.x * (blockDim.x >> 5) + (threadIdx.x >> 5);
    int lane = threadIdx.x & 31;
    if (row >= NB * NP) return;
    const float4* d4 = (const float4*)(dist + (size_t)row * NP);
    float v[32];
    #pragma unroll
    for (int s4 = 0; s4 < 8; s4++) {
        float4 t = d4[s4 * 32 + lane];
        v[4 * s4 + 0] = t.x; v[4 * s4 + 1] = t.y;
        v[4 * s4 + 2] = t.z; v[4 * s4 + 3] = t.w;
    }

    float m0 = -FLT_MAX, m1 = -FLT_MAX, m2 = -FLT_MAX, m3 = -FLT_MAX;
    int q0 = 0, q1 = 0, q2 = 0, q3 = 0;
    #pragma unroll
    for (int s = 0; s < 32; s++) {
        float x = v[s];
        if (x > m3) {
            if (x > m0)      { m3 = m2; q3 = q2; m2 = m1; q2 = q1; m1 = m0; q1 = q0; m0 = x; q0 = s; }
            else if (x > m1) { m3 = m2; q3 = q2; m2 = m1; q2 = q1; m1 = x;  q1 = s; }
            else if (x > m2) { m3 = m2; q3 = q2; m2 = x;  q2 = s; }
            else             { m3 = x;  q3 = s; }
        }
    }

    float thresh = 0.f;
    #pragma unroll
    for (int t = 0; t < KNN; t++) {
        float best = m0;
        #pragma unroll
        for (int off = 16; off; off >>= 1)
            best = fmaxf(best, __shfl_xor_sync(0xffffffffu, best, off));
        unsigned mask = __ballot_sync(0xffffffffu, m0 == best);
        int wl = __ffs(mask) - 1;
        int wq = __shfl_sync(0xffffffffu, q0, wl);
        if (lane == 0) idx[row * KNN + t] = (wq >> 2) * 128 + wl * 4 + (wq & 3);
        if (lane == wl) { m0 = m1; q0 = q1; m1 = m2; q1 = q2; m2 = m3; q2 = q3; m3 = -FLT_MAX; }
        thresh = best;
    }

    int cnt = 0;
    #pragma unroll
    for (int s = 0; s < 32; s++) cnt += (v[s] > thresh) ? 1 : 0;
    cnt = __reduce_add_sync(0xffffffffu, cnt);
    if (cnt == 19) return;

    // rare fallback: exact iterative selection (same slot->element mapping)
    for (int t = 0; t < KNN; t++) {
        float best = -FLT_MAX; int bs = 0;
        #pragma unroll
        for (int s = 0; s < 32; s++)
            if (v[s] > best) { best = v[s]; bs = s; }
        int bj = (bs >> 2) * 128 + lane * 4 + (bs & 3);
        #pragma unroll
        for (int off = 16; off; off >>= 1) {
            float ov = __shfl_xor_sync(0xffffffffu, best, off);
            int oj = __shfl_xor_sync(0xffffffffu, bj, off);
            if (ov > best || (ov == best && oj < bj)) { best = ov; bj = oj; }
        }
        if (lane == 0) idx[row * KNN + t] = bj;
        // winner clears its slot: element bj belongs to lane (bj>>2)&31
        if (((bj >> 2) & 31) == lane) {
            int ks = (bj >> 7) * 4 + (bj & 3);
            #pragma unroll
            for (int s = 0; s < 32; s++)
                if (s == ks) v[s] = -FLT_MAX;
        }
    }
}

// =================== edge aggregate (float4) ===================
__global__ void aggregate_kernel(const float* __restrict__ ab, int O,
                                 const float* __restrict__ bias,
                                 const int* __restrict__ idx,
                                 float* __restrict__ out, int ldo, int ooff)
{
    int bi = blockIdx.x;
    int b = bi >> 10, i = bi & 1023;
    __shared__ int sj[KNN];
    if (threadIdx.x < KNN) sj[threadIdx.x] = idx[bi * KNN + threadIdx.x];
    __syncthreads();
    const float* abb = ab + (size_t)b * NP * 2 * O;
    int nch = O >> 2;
    for (int t = threadIdx.x; t < nch; t += blockDim.x) {
        float4 a4 = *(const float4*)(abb + (size_t)i * 2 * O + t * 4);
        float4 bi4 = *(const float4*)(bias + t * 4);
        a4.x += bi4.x; a4.y += bi4.y; a4.z += bi4.z; a4.w += bi4.w;
        float4 acc = {0.f, 0.f, 0.f, 0.f};
        #pragma unroll
        for (int k = 0; k < KNN; k++) {
            float4 b4 = *(const float4*)(abb + (size_t)sj[k] * 2 * O + O + t * 4);
            float vx = a4.x + b4.x; acc.x += fmaxf(vx, 0.2f * vx);
            float vy = a4.y + b4.y; acc.y += fmaxf(vy, 0.2f * vy);
            float vz = a4.z + b4.z; acc.z += fmaxf(vz, 0.2f * vz);
            float vw = a4.w + b4.w; acc.w += fmaxf(vw, 0.2f * vw);
        }
        acc.x *= 0.05f; acc.y *= 0.05f; acc.z *= 0.05f; acc.w *= 0.05f;
        *(float4*)(out + ((size_t)b * NP + i) * ldo + ooff + t * 4) = acc;
    }
}

// =================== pooling + final linear ===================
__global__ void pool_kernel(const float* __restrict__ hf, float* __restrict__ pooled)
{
    int b = blockIdx.x;
    int t = threadIdx.x;                 // 128 threads, each owns 4 channels
    float4 s = {0.f, 0.f, 0.f, 0.f};
    const float* base = hf + (size_t)b * NP * 512 + t * 4;
    for (int i = 0; i < NP; i++) {
        float4 x = *(const float4*)(base + (size_t)i * 512);
        s.x += x.x; s.y += x.y; s.z += x.z; s.w += x.w;
    }
    s.x *= (1.f / NP); s.y *= (1.f / NP); s.z *= (1.f / NP); s.w *= (1.f / NP);
    *(float4*)(pooled + b * 512 + t * 4) = s;
}

__global__ void final_kernel(const float* __restrict__ pooled, const float* __restrict__ We,
                             float* __restrict__ out)
{
    int b = blockIdx.x, e = threadIdx.x;
    const float* p = pooled + b * 512;
    const float* w = We + e * 512;
    float s = 0.f;
    for (int o = 0; o < 512; o++) s += p[o] * w[o];
    out[b * 256 + e] = s;
}

// =================== host side ===================
struct LayerCfg { int C, O, coff; const float *W, *g, *be, *m, *v; };

extern "C" void kernel_launch(void* const* d_in, const int* in_sizes, int n_in,
                              void* d_out, int out_size)
{
    const float* x  = (const float*)d_in[0];
    const float* We = (const float*)d_in[21];

    float *dist, *xx, *cat, *ab, *hf, *pooled, *bias4;
    int* idx;
    __nv_bfloat16 *s1, *s2, *wabs4;
    cudaGetSymbolAddress((void**)&dist,   g_dist);
    cudaGetSymbolAddress((void**)&idx,    g_idx);
    cudaGetSymbolAddress((void**)&xx,     g_xx);
    cudaGetSymbolAddress((void**)&cat,    g_cat);
    cudaGetSymbolAddress((void**)&ab,     g_ab);
    cudaGetSymbolAddress((void**)&hf,     g_hf);
    cudaGetSymbolAddress((void**)&pooled, g_pooled);
    cudaGetSymbolAddress((void**)&bias4,  g_bias4);
    cudaGetSymbolAddress((void**)&s1,     g_s1);
    cudaGetSymbolAddress((void**)&s2,     g_s2);
    cudaGetSymbolAddress((void**)&wabs4,  g_wabs4);

    static cudaStream_t sB = nullptr;
    static cudaEvent_t evRoot, evS[4], evB[4];
    static bool attrSet = false;
    if (!sB) {
        cudaStreamCreateWithFlags(&sB, cudaStreamNonBlocking);
        cudaEventCreateWithFlags(&evRoot, cudaEventDisableTiming);
        for (int i = 0; i < 4; i++) {
            cudaEventCreateWithFlags(&evS[i], cudaEventDisableTiming);
            cudaEventCreateWithFlags(&evB[i], cudaEventDisableTiming);
        }
    }
    if (!attrSet) {
        cudaFuncSetAttribute(mma_gemm_kernel,
                             cudaFuncAttributeMaxDynamicSharedMemorySize, GEMM_SMEM);
        attrSet = true;
    }

    LayerCfg L[4] = {
        {  3,  64,   0, (const float*)d_in[1],  (const float*)d_in[2],  (const float*)d_in[3],  (const float*)d_in[4],  (const float*)d_in[5]  },
        { 64, 128,   0, (const float*)d_in[6],  (const float*)d_in[7],  (const float*)d_in[8],  (const float*)d_in[9],  (const float*)d_in[10] },
        {128, 256,  64, (const float*)d_in[11], (const float*)d_in[12], (const float*)d_in[13], (const float*)d_in[14], (const float*)d_in[15] },
        {448, 512,   0, (const float*)d_in[16], (const float*)d_in[17], (const float*)d_in[18], (const float*)d_in[19], (const float*)d_in[20] },
    };
    int ooffs[4] = {0, 64, 192, 0};

    cudaEventRecord(evRoot, 0);
    cudaStreamWaitEvent(sB, evRoot, 0);

    for (int i = 0; i < 4; i++) {
        int Kp = ((3 * L[i].C + 63) / 64) * 64;
        wfoldsplit_kernel<<<2 * L[i].O, 128, 0, sB>>>(
            L[i].W, L[i].g, L[i].be, L[i].m, L[i].v, L[i].O, L[i].C, Kp,
            wabs4 + (size_t)i * 1024 * KPMAX, bias4 + i * 512);
    }

    for (int i = 0; i < 4; i++) {
        int C = L[i].C, O = L[i].O, coff = L[i].coff;
        int Kp = ((3 * C + 63) / 64) * 64;
        const float* hin = (i == 0) ? x : cat;
        int ld = (i == 0) ? 3 : 448;
        float* outbuf = (i == 3) ? hf : cat;
        int ldo = (i == 3) ? 512 : 448;

        split_kernel<<<NB * NP, 128>>>(hin, ld, coff, C, (long long)NP * ld, NP,
                                       s1, s2, Kp, xx);
        cudaEventRecord(evS[i], 0);

        cudaStreamWaitEvent(sB, evS[i], 0);
        dim3 gw((2 * O) / 128, NP / 128, NB);
        mma_gemm_kernel<<<gw, 256, GEMM_SMEM, sB>>>(
            s1, wabs4 + (size_t)i * 1024 * KPMAX, Kp,
            (long long)NP * Kp, 0, nullptr, 1, ab, 2 * O);
        cudaEventRecord(evB[i], sB);

        dim3 gd(NP / 128, NP / 128, NB);
        mma_gemm_kernel<<<gd, 256, GEMM_SMEM>>>(
            s1, s2, Kp, (long long)NP * Kp, (long long)NP * Kp,
            xx, 0, dist, NP);
        topk_kernel<<<NB * NP / 8, 256>>>(dist, idx);

        cudaStreamWaitEvent(0, evB[i], 0);
        int bt = (O >> 2) < 128 ? (O >> 2) : 128;
        if (bt < 32) bt = 32;
        aggregate_kernel<<<NB * NP, bt>>>(ab, O, bias4 + i * 512, idx,
                                          outbuf, ldo, ooffs[i]);
    }

    pool_kernel<<<NB, 128>>>(hf, pooled);
    final_kernel<<<NB, 256>>>(pooled, We, (float*)d_out);
}

// round 13
// speedup vs baseline: 1.0429x; 1.0266x over previous
#include <cuda_runtime.h>
#include <cuda_bf16.h>
#include <math.h>
#include <float.h>
#include <stdint.h>

#define NB 8
#define NP 1024
#define KNN 20
#define HLMAX 896            // 2*448: [hi|lo] width for the largest layer

// ---------------- scratch (device globals; no allocation allowed) ----------------
__device__ __align__(16) float g_dist[NB * NP * NP];            // 32 MB
__device__ __align__(16) int   g_idx[NB * NP * KNN];
__device__ __align__(16) float g_xx[NB * NP];
__device__ __align__(16) float g_cat[NB * NP * 448];
__device__ __align__(16) float g_ab[NB * NP * 1024];
__device__ __align__(16) float g_hf[NB * NP * 512];
__device__ __align__(16) float g_pooled[NB * 512];
__device__ __align__(16) float g_bias4[4 * 512];
__device__ __align__(16) __nv_bfloat16 g_hl[NB * NP * HLMAX];    // features [hi|lo]
__device__ __align__(16) __nv_bfloat16 g_whl4[4][1024 * HLMAX];  // per-layer folded weights [hi|lo]

// =================== helpers ===================
__device__ __forceinline__ uint32_t smem_u32(const void* p) {
    uint32_t a;
    asm("{ .reg .u64 t; cvta.to.shared.u64 t, %1; cvt.u32.u64 %0, t; }" : "=r"(a) : "l"(p));
    return a;
}
__device__ __forceinline__ void cpa16(uint32_t s, const void* g) {
    asm volatile("cp.async.cg.shared.global [%0], [%1], 16;" :: "r"(s), "l"(g));
}
#define CP_COMMIT() asm volatile("cp.async.commit_group;")
#define CP_WAIT2()  asm volatile("cp.async.wait_group 2;")
#define CP_WAIT1()  asm volatile("cp.async.wait_group 1;")
#define CP_WAIT0()  asm volatile("cp.async.wait_group 0;")

__device__ __forceinline__ void ldsm_x4(uint32_t* r, uint32_t addr) {
    asm volatile("ldmatrix.sync.aligned.m8n8.x4.shared.b16 {%0,%1,%2,%3}, [%4];"
        : "=r"(r[0]), "=r"(r[1]), "=r"(r[2]), "=r"(r[3]) : "r"(addr));
}

// =================== feature split -> [hi(Cp) | lo(Cp)] + fused norms ===================
__global__ void split_kernel(const float* __restrict__ src, int ld, int coff, int C,
                             long long bstride, int rows_per_b,
                             __nv_bfloat16* __restrict__ hl, int Cp,
                             float* __restrict__ xxout)
{
    __shared__ float red[4];
    int r = blockIdx.x;
    int b = r / rows_per_b;
    int ri = r - b * rows_per_b;
    const float* p = src + (long long)b * bstride + (long long)ri * ld + coff;
    __nv_bfloat16* o = hl + (long long)r * 2 * Cp;
    __nv_bfloat16 z = __float2bfloat16(0.f);
    float ss = 0.f;
    for (int k = threadIdx.x; k < 2 * Cp; k += blockDim.x) {
        bool isHi = k < Cp;
        int c = isHi ? k : k - Cp;
        __nv_bfloat16 vv = z;
        if (c < C) {
            float x = p[c];
            if (isHi) ss += x * x;
            __nv_bfloat16 hi = __float2bfloat16(x);
            vv = isHi ? hi : __float2bfloat16(x - __bfloat162float(hi));
        }
        o[k] = vv;
    }
    int lane = threadIdx.x & 31, w = threadIdx.x >> 5;
    #pragma unroll
    for (int of = 16; of; of >>= 1) ss += __shfl_xor_sync(0xffffffffu, ss, of);
    if (!lane) red[w] = ss;
    __syncthreads();
    if (threadIdx.x == 0)
        xxout[r] = red[0] + red[1] + red[2] + red[3];
}

// =================== fold BN into weights -> [hi(Cp) | lo(Cp)] ===================
// row r < O : s*(Wd - Wc) ('a' projection);  r >= O : s*Wc ('b' projection)
__global__ void wfoldsplit_kernel(const float* __restrict__ W, const float* __restrict__ g,
                                  const float* __restrict__ be, const float* __restrict__ m,
                                  const float* __restrict__ v, int O, int C, int Cp,
                                  __nv_bfloat16* __restrict__ whl,
                                  float* __restrict__ bias)
{
    int r = blockIdx.x;                 // 0 .. 2O-1
    bool isA = r < O;
    int o = isA ? r : r - O;
    float s = g[o] * rsqrtf(v[o] + 1e-5f);
    if (threadIdx.x == 0 && isA) bias[o] = be[o] - s * m[o];
    __nv_bfloat16* out = whl + (long long)r * 2 * Cp;
    __nv_bfloat16 z = __float2bfloat16(0.f);
    for (int k = threadIdx.x; k < 2 * Cp; k += blockDim.x) {
        bool isHi = k < Cp;
        int c = isHi ? k : k - Cp;
        __nv_bfloat16 vv = z;
        if (c < C) {
            float wc = W[o * 2 * C + c];
            float wd = W[o * 2 * C + C + c];
            float val = isA ? s * (wd - wc) : s * wc;
            __nv_bfloat16 hi = __float2bfloat16(val);
            vv = isHi ? hi : __float2bfloat16(val - __bfloat162float(hi));
        }
        out[k] = vv;
    }
}

// =================== mma.sync bf16 GEMM over virtual K = 3*Cp ===================
// A virtual layout [hi|lo|hi]: chunk offset ka<2Cp ? ka : ka-2Cp  (into [hi|lo])
// B virtual layout [hi|hi|lo]: chunk offset ka<Cp  ? ka : ka-Cp
// => D = hh + lh + hl ≈ fp32 product. mode 0: dist epilogue; mode 1: plain store.
#define SSTR 56
#define ASZ  (128 * SSTR)
#define NSTAGE 3
#define GEMM_SMEM (NSTAGE * ASZ * 2 * 2)

__device__ __forceinline__ void mma16816(float* c, const uint32_t* a, const uint32_t* b)
{
    asm volatile(
        "mma.sync.aligned.m16n8k16.row.col.f32.bf16.bf16.f32 "
        "{%0,%1,%2,%3}, {%4,%5,%6,%7}, {%8,%9}, {%0,%1,%2,%3};"
        : "+f"(c[0]), "+f"(c[1]), "+f"(c[2]), "+f"(c[3])
        : "r"(a[0]), "r"(a[1]), "r"(a[2]), "r"(a[3]), "r"(b[0]), "r"(b[1]));
}

__global__ __launch_bounds__(256, 2) void mma_gemm_kernel(
    const __nv_bfloat16* __restrict__ A,
    const __nv_bfloat16* __restrict__ Bm,
    int Cp, long long bsA, long long bsB,
    const float* __restrict__ xx, int mode,
    float* __restrict__ out, int ldo)
{
    extern __shared__ __align__(16) __nv_bfloat16 sm[];
    __nv_bfloat16* As = sm;
    __nv_bfloat16* Bs = sm + NSTAGE * ASZ;

    int b = blockIdx.z;
    int row0 = blockIdx.y * 128;
    int col0 = blockIdx.x * 128;
    int tid = threadIdx.x;
    int wid = tid >> 5, lane = tid & 31;
    int wm = (wid >> 2) * 64;
    int wn = (wid & 3) * 32;

    int ld2 = 2 * Cp;
    int nk = (3 * Cp) >> 5;

    const __nv_bfloat16* Ab = A + (long long)b * bsA;
    const __nv_bfloat16* Bb = Bm + (long long)b * bsB;

    int lr = tid >> 1;
    int lc = (tid & 1) * 16;

    uint32_t sAraw = smem_u32(As);
    uint32_t sBraw = smem_u32(Bs);
    uint32_t sA0 = sAraw + (uint32_t)(lr * SSTR + lc) * 2;
    uint32_t sB0 = sBraw + (uint32_t)(lr * SSTR + lc) * 2;
    const __nv_bfloat16* gA = Ab + (long long)(row0 + lr) * ld2 + lc;
    const __nv_bfloat16* gB = Bb + (long long)(col0 + lr) * ld2 + lc;

    uint32_t a_off = (uint32_t)((wm + (lane & 15)) * SSTR + (lane >> 4) * 8);
    uint32_t b_off = (uint32_t)((wn + (lane & 7) + ((lane >> 4) & 1) * 8) * SSTR
                                + ((lane >> 3) & 1) * 8);

    #pragma unroll
    for (int s = 0; s < NSTAGE - 1; s++) {
        if (s < nk) {
            int ka = s * 32;
            int koffA = (ka < 2 * Cp) ? ka : ka - 2 * Cp;
            int koffB = (ka < Cp) ? ka : ka - Cp;
            uint32_t da = sA0 + (uint32_t)(s * ASZ) * 2;
            uint32_t db = sB0 + (uint32_t)(s * ASZ) * 2;
            cpa16(da, gA + koffA); cpa16(da + 16, gA + koffA + 8);
            cpa16(db, gB + koffB); cpa16(db + 16, gB + koffB + 8);
            CP_COMMIT();
        }
    }

    float acc[4][4][4] = {};

    for (int kc = 0; kc < nk; kc++) {
        int cur = kc % NSTAGE;
        if (kc + 2 < nk) {
            int nxt = (kc + 2) % NSTAGE;
            int ka = (kc + 2) * 32;
            int koffA = (ka < 2 * Cp) ? ka : ka - 2 * Cp;
            int koffB = (ka < Cp) ? ka : ka - Cp;
            uint32_t da = sA0 + (uint32_t)(nxt * ASZ) * 2;
            uint32_t db = sB0 + (uint32_t)(nxt * ASZ) * 2;
            cpa16(da, gA + koffA); cpa16(da + 16, gA + koffA + 8);
            cpa16(db, gB + koffB); cpa16(db + 16, gB + koffB + 8);
            CP_COMMIT();
            CP_WAIT2();
        } else if (kc + 1 < nk) {
            CP_WAIT1();
        } else {
            CP_WAIT0();
        }
        __syncthreads();

        uint32_t aCur = sAraw + (uint32_t)(cur * ASZ) * 2 + a_off * 2;
        uint32_t bCur = sBraw + (uint32_t)(cur * ASZ) * 2 + b_off * 2;
        #pragma unroll
        for (int kk = 0; kk < 32; kk += 16) {
            uint32_t af[4][4], bq[2][4];
            #pragma unroll
            for (int mf = 0; mf < 4; mf++)
                ldsm_x4(af[mf], aCur + (uint32_t)(mf * 16 * SSTR + kk) * 2);
            #pragma unroll
            for (int nq = 0; nq < 2; nq++)
                ldsm_x4(bq[nq], bCur + (uint32_t)(nq * 16 * SSTR + kk) * 2);
            #pragma unroll
            for (int mf = 0; mf < 4; mf++)
                #pragma unroll
                for (int nf = 0; nf < 4; nf++)
                    mma16816(acc[mf][nf], af[mf], &bq[nf >> 1][(nf & 1) * 2]);
        }
        __syncthreads();
    }

    int ar = lane >> 2, ac = (lane & 3) * 2;
    if (mode == 0) {
        const float* xxb = xx + b * NP;
        #pragma unroll
        for (int mf = 0; mf < 4; mf++) {
            int r0g = row0 + wm + mf * 16 + ar;
            float xi0 = xxb[r0g], xi1 = xxb[r0g + 8];
            #pragma unroll
            for (int nf = 0; nf < 4; nf++) {
                int cg = col0 + wn + nf * 8 + ac;
                float* acc4 = acc[mf][nf];
                float xj0 = xxb[cg], xj1 = xxb[cg + 1];
                float2 v0, v1;
                v0.x = 2.f * acc4[0] - xi0 - xj0;
                v0.y = 2.f * acc4[1] - xi0 - xj1;
                v1.x = 2.f * acc4[2] - xi1 - xj0;
                v1.y = 2.f * acc4[3] - xi1 - xj1;
                *(float2*)(out + ((long long)b * NP + r0g) * ldo + cg) = v0;
                *(float2*)(out + ((long long)b * NP + r0g + 8) * ldo + cg) = v1;
            }
        }
    } else {
        #pragma unroll
        for (int mf = 0; mf < 4; mf++) {
            int r0g = row0 + wm + mf * 16 + ar;
            #pragma unroll
            for (int nf = 0; nf < 4; nf++) {
                int cg = col0 + wn + nf * 8 + ac;
                float* acc4 = acc[mf][nf];
                float2 v0, v1;
                v0.x = acc4[0]; v0.y = acc4[1];
                v1.x = acc4[2]; v1.y = acc4[3];
                *(float2*)(out + ((long long)b * NP + r0g) * ldo + cg) = v0;
                *(float2*)(out + ((long long)b * NP + r0g + 8) * ldo + cg) = v1;
            }
        }
    }
}

// =================== top-20 (R10-proven): sorted top-4 queues + verify ===================
__global__ void topk_kernel(const float* __restrict__ dist, int* __restrict__ idx)
{
    int row = blockIdx.x * (blockDim.x >> 5) + (threadIdx.x >> 5);
    int lane = threadIdx.x & 31;
    if (row >= NB * NP) return;
    const float* d = dist + (size_t)row * NP;
    float v[32];
    #pragma unroll
    for (int s = 0; s < 32; s++) v[s] = d[s * 32 + lane];

    float m0 = -FLT_MAX, m1 = -FLT_MAX, m2 = -FLT_MAX, m3 = -FLT_MAX;
    int q0 = 0, q1 = 0, q2 = 0, q3 = 0;
    #pragma unroll
    for (int s = 0; s < 32; s++) {
        float x = v[s];
        if (x > m3) {
            if (x > m0)      { m3 = m2; q3 = q2; m2 = m1; q2 = q1; m1 = m0; q1 = q0; m0 = x; q0 = s; }
            else if (x > m1) { m3 = m2; q3 = q2; m2 = m1; q2 = q1; m1 = x;  q1 = s; }
            else if (x > m2) { m3 = m2; q3 = q2; m2 = x;  q2 = s; }
            else             { m3 = x;  q3 = s; }
        }
    }

    float thresh = 0.f;
    #pragma unroll
    for (int t = 0; t < KNN; t++) {
        float best = m0;
        #pragma unroll
        for (int off = 16; off; off >>= 1)
            best = fmaxf(best, __shfl_xor_sync(0xffffffffu, best, off));
        unsigned mask = __ballot_sync(0xffffffffu, m0 == best);
        int wl = __ffs(mask) - 1;
        int wq = __shfl_sync(0xffffffffu, q0, wl);
        if (lane == 0) idx[row * KNN + t] = wq * 32 + wl;
        if (lane == wl) { m0 = m1; q0 = q1; m1 = m2; q1 = q2; m2 = m3; q2 = q3; m3 = -FLT_MAX; }
        thresh = best;
    }

    int cnt = 0;
    #pragma unroll
    for (int s = 0; s < 32; s++) cnt += (v[s] > thresh) ? 1 : 0;
    cnt = __reduce_add_sync(0xffffffffu, cnt);
    if (cnt == 19) return;

    // rare fallback: exact iterative selection (element = s*32 + lane)
    for (int t = 0; t < KNN; t++) {
        float best = -FLT_MAX; int bs = 0;
        #pragma unroll
        for (int s = 0; s < 32; s++)
            if (v[s] > best) { best = v[s]; bs = s; }
        int bj = bs * 32 + lane;
        #pragma unroll
        for (int off = 16; off; off >>= 1) {
            float ov = __shfl_xor_sync(0xffffffffu, best, off);
            int oj = __shfl_xor_sync(0xffffffffu, bj, off);
            if (ov > best || (ov == best && oj < bj)) { best = ov; bj = oj; }
        }
        if (lane == 0) idx[row * KNN + t] = bj;
        if ((bj & 31) == lane) {
            int ks = bj >> 5;
            #pragma unroll
            for (int s = 0; s < 32; s++)
                if (s == ks) v[s] = -FLT_MAX;
        }
    }
}

// =================== edge aggregate (R10-proven scalar) ===================
__global__ void aggregate_kernel(const float* __restrict__ ab, int O,
                                 const float* __restrict__ bias,
                                 const int* __restrict__ idx,
                                 float* __restrict__ out, int ldo, int ooff)
{
    int bi = blockIdx.x;
    int b = bi >> 10, i = bi & 1023;
    __shared__ int sj[KNN];
    if (threadIdx.x < KNN) sj[threadIdx.x] = idx[bi * KNN + threadIdx.x];
    __syncthreads();
    const float* abb = ab + (size_t)b * NP * 2 * O;
    for (int o = threadIdx.x; o < O; o += blockDim.x) {
        float a = abb[(size_t)i * 2 * O + o] + bias[o];
        float acc = 0.f;
        #pragma unroll
        for (int k = 0; k < KNN; k++) {
            float val = a + abb[(size_t)sj[k] * 2 * O + O + o];
            acc += fmaxf(val, 0.2f * val);
        }
        out[((size_t)b * NP + i) * ldo + ooff + o] = acc * 0.05f;
    }
}

// =================== pooling + final linear (R10-proven) ===================
__global__ void pool_kernel(const float* __restrict__ hf, float* __restrict__ pooled)
{
    int b = blockIdx.x;
    int o = blockIdx.y * blockDim.x + threadIdx.x;
    float s = 0.f;
    for (int i = 0; i < NP; i++) s += hf[((size_t)b * NP + i) * 512 + o];
    pooled[b * 512 + o] = s * (1.f / NP);
}

__global__ void final_kernel(const float* __restrict__ pooled, const float* __restrict__ We,
                             float* __restrict__ out)
{
    int b = blockIdx.x, e = threadIdx.x;
    const float* p = pooled + b * 512;
    const float* w = We + e * 512;
    float s = 0.f;
    for (int o = 0; o < 512; o++) s += p[o] * w[o];
    out[b * 256 + e] = s;
}

// =================== host side ===================
struct LayerCfg { int C, Cp, O, coff; const float *W, *g, *be, *m, *v; };

extern "C" void kernel_launch(void* const* d_in, const int* in_sizes, int n_in,
                              void* d_out, int out_size)
{
    const float* x  = (const float*)d_in[0];
    const float* We = (const float*)d_in[21];

    float *dist, *xx, *cat, *ab, *hf, *pooled, *bias4;
    int* idx;
    __nv_bfloat16 *hl, *whl4;
    cudaGetSymbolAddress((void**)&dist,   g_dist);
    cudaGetSymbolAddress((void**)&idx,    g_idx);
    cudaGetSymbolAddress((void**)&xx,     g_xx);
    cudaGetSymbolAddress((void**)&cat,    g_cat);
    cudaGetSymbolAddress((void**)&ab,     g_ab);
    cudaGetSymbolAddress((void**)&hf,     g_hf);
    cudaGetSymbolAddress((void**)&pooled, g_pooled);
    cudaGetSymbolAddress((void**)&bias4,  g_bias4);
    cudaGetSymbolAddress((void**)&hl,     g_hl);
    cudaGetSymbolAddress((void**)&whl4,   g_whl4);

    static cudaStream_t sB = nullptr;
    static cudaEvent_t evRoot, evS[4], evB[4];
    static bool attrSet = false;
    if (!sB) {
        cudaStreamCreateWithFlags(&sB, cudaStreamNonBlocking);
        cudaEventCreateWithFlags(&evRoot, cudaEventDisableTiming);
        for (int i = 0; i < 4; i++) {
            cudaEventCreateWithFlags(&evS[i], cudaEventDisableTiming);
            cudaEventCreateWithFlags(&evB[i], cudaEventDisableTiming);
        }
    }
    if (!attrSet) {
        cudaFuncSetAttribute(mma_gemm_kernel,
                             cudaFuncAttributeMaxDynamicSharedMemorySize, GEMM_SMEM);
        attrSet = true;
    }

    LayerCfg L[4] = {
        {  3,  32,  64,   0, (const float*)d_in[1],  (const float*)d_in[2],  (const float*)d_in[3],  (const float*)d_in[4],  (const float*)d_in[5]  },
        { 64,  64, 128,   0, (const float*)d_in[6],  (const float*)d_in[7],  (const float*)d_in[8],  (const float*)d_in[9],  (const float*)d_in[10] },
        {128, 128, 256,  64, (const float*)d_in[11], (const float*)d_in[12], (const float*)d_in[13], (const float*)d_in[14], (const float*)d_in[15] },
        {448, 448, 512,   0, (const float*)d_in[16], (const float*)d_in[17], (const float*)d_in[18], (const float*)d_in[19], (const float*)d_in[20] },
    };
    int ooffs[4] = {0, 64, 192, 0};

    cudaEventRecord(evRoot, 0);
    cudaStreamWaitEvent(sB, evRoot, 0);

    for (int i = 0; i < 4; i++) {
        wfoldsplit_kernel<<<2 * L[i].O, 128, 0, sB>>>(
            L[i].W, L[i].g, L[i].be, L[i].m, L[i].v, L[i].O, L[i].C, L[i].Cp,
            whl4 + (size_t)i * 1024 * HLMAX, bias4 + i * 512);
    }

    for (int i = 0; i < 4; i++) {
        int C = L[i].C, Cp = L[i].Cp, O = L[i].O, coff = L[i].coff;
        const float* hin = (i == 0) ? x : cat;
        int ld = (i == 0) ? 3 : 448;
        float* outbuf = (i == 3) ? hf : cat;
        int ldo = (i == 3) ? 512 : 448;

        split_kernel<<<NB * NP, 128>>>(hin, ld, coff, C, (long long)NP * ld, NP,
                                       hl, Cp, xx);
        cudaEventRecord(evS[i], 0);

        cudaStreamWaitEvent(sB, evS[i], 0);
        dim3 gw((2 * O) / 128, NP / 128, NB);
        mma_gemm_kernel<<<gw, 256, GEMM_SMEM, sB>>>(
            hl, whl4 + (size_t)i * 1024 * HLMAX, Cp,
            (long long)NP * 2 * Cp, 0, nullptr, 1, ab, 2 * O);
        cudaEventRecord(evB[i], sB);

        dim3 gd(NP / 128, NP / 128, NB);
        mma_gemm_kernel<<<gd, 256, GEMM_SMEM>>>(
            hl, hl, Cp, (long long)NP * 2 * Cp, (long long)NP * 2 * Cp,
            xx, 0, dist, NP);
        topk_kernel<<<NB * NP / 8, 256>>>(dist, idx);

        cudaStreamWaitEvent(0, evB[i], 0);
        int bt = O < 256 ? O : 256;
        aggregate_kernel<<<NB * NP, bt>>>(ab, O, bias4 + i * 512, idx,
                                          outbuf, ldo, ooffs[i]);
    }

    pool_kernel<<<dim3(NB, 2), 256>>>(hf, pooled);
    final_kernel<<<NB, 256>>>(pooled, We, (float*)d_out);
}

// round 14
// speedup vs baseline: 1.1450x; 1.0979x over previous
#include <cuda_runtime.h>
#include <cuda_bf16.h>
#include <math.h>
#include <float.h>
#include <stdint.h>

#define NB 8
#define NP 1024
#define KNN 20
#define HLMAX 896            // 2*448: [hi|lo] width for the largest layer

// ---------------- scratch (device globals; no allocation allowed) ----------------
__device__ __align__(16) float g_dist[NB * NP * NP];            // 32 MB
__device__ __align__(16) int   g_idx[NB * NP * KNN];
__device__ __align__(16) float g_xx[NB * NP];
__device__ __align__(16) float g_cat[NB * NP * 448];
__device__ __align__(16) float g_ab[NB * NP * 1024];
__device__ __align__(16) float g_hf[NB * NP * 512];
__device__ __align__(16) float g_pooled[NB * 512];
__device__ __align__(16) float g_bias4[4 * 512];
__device__ __align__(16) __nv_bfloat16 g_hl[NB * NP * HLMAX];    // features [hi|lo]
__device__ __align__(16) __nv_bfloat16 g_whl4[4][1024 * HLMAX];  // per-layer folded weights [hi|lo]

// =================== helpers ===================
__device__ __forceinline__ uint32_t smem_u32(const void* p) {
    uint32_t a;
    asm("{ .reg .u64 t; cvta.to.shared.u64 t, %1; cvt.u32.u64 %0, t; }" : "=r"(a) : "l"(p));
    return a;
}
__device__ __forceinline__ void cpa16(uint32_t s, const void* g) {
    asm volatile("cp.async.cg.shared.global [%0], [%1], 16;" :: "r"(s), "l"(g));
}
#define CP_COMMIT() asm volatile("cp.async.commit_group;")
#define CP_WAIT2()  asm volatile("cp.async.wait_group 2;")
#define CP_WAIT1()  asm volatile("cp.async.wait_group 1;")
#define CP_WAIT0()  asm volatile("cp.async.wait_group 0;")

__device__ __forceinline__ void ldsm_x4(uint32_t* r, uint32_t addr) {
    asm volatile("ldmatrix.sync.aligned.m8n8.x4.shared.b16 {%0,%1,%2,%3}, [%4];"
        : "=r"(r[0]), "=r"(r[1]), "=r"(r[2]), "=r"(r[3]) : "r"(addr));
}

// =================== feature split -> [hi(Cp) | lo(Cp)] + fused norms ===================
__global__ void split_kernel(const float* __restrict__ src, int ld, int coff, int C,
                             long long bstride, int rows_per_b,
                             __nv_bfloat16* __restrict__ hl, int Cp,
                             float* __restrict__ xxout)
{
    __shared__ float red[4];
    int r = blockIdx.x;
    int b = r / rows_per_b;
    int ri = r - b * rows_per_b;
    const float* p = src + (long long)b * bstride + (long long)ri * ld + coff;
    __nv_bfloat16* o = hl + (long long)r * 2 * Cp;
    __nv_bfloat16 z = __float2bfloat16(0.f);
    float ss = 0.f;
    for (int k = threadIdx.x; k < 2 * Cp; k += blockDim.x) {
        bool isHi = k < Cp;
        int c = isHi ? k : k - Cp;
        __nv_bfloat16 vv = z;
        if (c < C) {
            float x = p[c];
            if (isHi) ss += x * x;
            __nv_bfloat16 hi = __float2bfloat16(x);
            vv = isHi ? hi : __float2bfloat16(x - __bfloat162float(hi));
        }
        o[k] = vv;
    }
    int lane = threadIdx.x & 31, w = threadIdx.x >> 5;
    #pragma unroll
    for (int of = 16; of; of >>= 1) ss += __shfl_xor_sync(0xffffffffu, ss, of);
    if (!lane) red[w] = ss;
    __syncthreads();
    if (threadIdx.x == 0)
        xxout[r] = red[0] + red[1] + red[2] + red[3];
}

// =================== fold BN into weights -> [hi(Cp) | lo(Cp)] ===================
__global__ void wfoldsplit_kernel(const float* __restrict__ W, const float* __restrict__ g,
                                  const float* __restrict__ be, const float* __restrict__ m,
                                  const float* __restrict__ v, int O, int C, int Cp,
                                  __nv_bfloat16* __restrict__ whl,
                                  float* __restrict__ bias)
{
    int r = blockIdx.x;                 // 0 .. 2O-1
    bool isA = r < O;
    int o = isA ? r : r - O;
    float s = g[o] * rsqrtf(v[o] + 1e-5f);
    if (threadIdx.x == 0 && isA) bias[o] = be[o] - s * m[o];
    __nv_bfloat16* out = whl + (long long)r * 2 * Cp;
    __nv_bfloat16 z = __float2bfloat16(0.f);
    for (int k = threadIdx.x; k < 2 * Cp; k += blockDim.x) {
        bool isHi = k < Cp;
        int c = isHi ? k : k - Cp;
        __nv_bfloat16 vv = z;
        if (c < C) {
            float wc = W[o * 2 * C + c];
            float wd = W[o * 2 * C + C + c];
            float val = isA ? s * (wd - wc) : s * wc;
            __nv_bfloat16 hi = __float2bfloat16(val);
            vv = isHi ? hi : __float2bfloat16(val - __bfloat162float(hi));
        }
        out[k] = vv;
    }
}

// =================== mma.sync bf16 GEMM over virtual K = 3*Cp ===================
// A virtual [hi|lo|hi]; B virtual [hi|hi|lo] => D = hh + lh + hl ≈ fp32 product.
#define SSTR 56
#define ASZ  (128 * SSTR)
#define NSTAGE 3
#define GEMM_SMEM (NSTAGE * ASZ * 2 * 2)
#define TSTR 132            // transpose staging stride (floats)

__device__ __forceinline__ void mma16816(float* c, const uint32_t* a, const uint32_t* b)
{
    asm volatile(
        "mma.sync.aligned.m16n8k16.row.col.f32.bf16.bf16.f32 "
        "{%0,%1,%2,%3}, {%4,%5,%6,%7}, {%8,%9}, {%0,%1,%2,%3};"
        : "+f"(c[0]), "+f"(c[1]), "+f"(c[2]), "+f"(c[3])
        : "r"(a[0]), "r"(a[1]), "r"(a[2]), "r"(a[3]), "r"(b[0]), "r"(b[1]));
}

// mode 0: SYMMETRIC dist. gridDim.x = 36 (lower-triangle tiles bx<=by),
//         computes tile (row=by,col=bx), stores it and (if off-diag) its mirror.
// mode 1: plain weight projection, gridDim.x = 2O/128.
__global__ __launch_bounds__(256, 2) void mma_gemm_kernel(
    const __nv_bfloat16* __restrict__ A,
    const __nv_bfloat16* __restrict__ Bm,
    int Cp, long long bsA, long long bsB,
    const float* __restrict__ xx, int mode,
    float* __restrict__ out, int ldo)
{
    extern __shared__ __align__(16) __nv_bfloat16 sm[];
    __nv_bfloat16* As = sm;
    __nv_bfloat16* Bs = sm + NSTAGE * ASZ;

    int b = blockIdx.z;
    int row0, col0;
    bool mirror = false;
    if (mode == 0) {
        int t = blockIdx.x;            // 0..35 -> (bx<=by)
        int by = 0;
        while (t >= by + 1) { t -= by + 1; by++; }
        int bx = t;
        row0 = by * 128;
        col0 = bx * 128;
        mirror = (bx != by);
    } else {
        row0 = blockIdx.y * 128;
        col0 = blockIdx.x * 128;
    }
    if (mode == 0) row0 = row0, col0 = col0;  // (row from tri decode)
    else           row0 = blockIdx.y * 128;

    int tid = threadIdx.x;
    int wid = tid >> 5, lane = tid & 31;
    int wm = (wid >> 2) * 64;
    int wn = (wid & 3) * 32;

    int ld2 = 2 * Cp;
    int nk = (3 * Cp) >> 5;

    const __nv_bfloat16* Ab = A + (long long)b * bsA;
    const __nv_bfloat16* Bb = Bm + (long long)b * bsB;

    int lr = tid >> 1;
    int lc = (tid & 1) * 16;

    uint32_t sAraw = smem_u32(As);
    uint32_t sBraw = smem_u32(Bs);
    uint32_t sA0 = sAraw + (uint32_t)(lr * SSTR + lc) * 2;
    uint32_t sB0 = sBraw + (uint32_t)(lr * SSTR + lc) * 2;
    const __nv_bfloat16* gA = Ab + (long long)(row0 + lr) * ld2 + lc;
    const __nv_bfloat16* gB = Bb + (long long)(col0 + lr) * ld2 + lc;

    uint32_t a_off = (uint32_t)((wm + (lane & 15)) * SSTR + (lane >> 4) * 8);
    uint32_t b_off = (uint32_t)((wn + (lane & 7) + ((lane >> 4) & 1) * 8) * SSTR
                                + ((lane >> 3) & 1) * 8);

    #pragma unroll
    for (int s = 0; s < NSTAGE - 1; s++) {
        if (s < nk) {
            int ka = s * 32;
            int koffA = (ka < 2 * Cp) ? ka : ka - 2 * Cp;
            int koffB = (ka < Cp) ? ka : ka - Cp;
            uint32_t da = sA0 + (uint32_t)(s * ASZ) * 2;
            uint32_t db = sB0 + (uint32_t)(s * ASZ) * 2;
            cpa16(da, gA + koffA); cpa16(da + 16, gA + koffA + 8);
            cpa16(db, gB + koffB); cpa16(db + 16, gB + koffB + 8);
            CP_COMMIT();
        }
    }

    float acc[4][4][4] = {};

    for (int kc = 0; kc < nk; kc++) {
        int cur = kc % NSTAGE;
        if (kc + 2 < nk) {
            int nxt = (kc + 2) % NSTAGE;
            int ka = (kc + 2) * 32;
            int koffA = (ka < 2 * Cp) ? ka : ka - 2 * Cp;
            int koffB = (ka < Cp) ? ka : ka - Cp;
            uint32_t da = sA0 + (uint32_t)(nxt * ASZ) * 2;
            uint32_t db = sB0 + (uint32_t)(nxt * ASZ) * 2;
            cpa16(da, gA + koffA); cpa16(da + 16, gA + koffA + 8);
            cpa16(db, gB + koffB); cpa16(db + 16, gB + koffB + 8);
            CP_COMMIT();
            CP_WAIT2();
        } else if (kc + 1 < nk) {
            CP_WAIT1();
        } else {
            CP_WAIT0();
        }
        __syncthreads();

        uint32_t aCur = sAraw + (uint32_t)(cur * ASZ) * 2 + a_off * 2;
        uint32_t bCur = sBraw + (uint32_t)(cur * ASZ) * 2 + b_off * 2;
        #pragma unroll
        for (int kk = 0; kk < 32; kk += 16) {
            uint32_t af[4][4], bq[2][4];
            #pragma unroll
            for (int mf = 0; mf < 4; mf++)
                ldsm_x4(af[mf], aCur + (uint32_t)(mf * 16 * SSTR + kk) * 2);
            #pragma unroll
            for (int nq = 0; nq < 2; nq++)
                ldsm_x4(bq[nq], bCur + (uint32_t)(nq * 16 * SSTR + kk) * 2);
            #pragma unroll
            for (int mf = 0; mf < 4; mf++)
                #pragma unroll
                for (int nf = 0; nf < 4; nf++)
                    mma16816(acc[mf][nf], af[mf], &bq[nf >> 1][(nf & 1) * 2]);
        }
        __syncthreads();
    }

    int ar = lane >> 2, ac = (lane & 3) * 2;
    if (mode == 0) {
        const float* xxb = xx + b * NP;
        float* st = (float*)sm;   // reuse pipeline smem for transpose staging
        #pragma unroll
        for (int mf = 0; mf < 4; mf++) {
            int r0g = row0 + wm + mf * 16 + ar;
            float xi0 = xxb[r0g], xi1 = xxb[r0g + 8];
            #pragma unroll
            for (int nf = 0; nf < 4; nf++) {
                int cg = col0 + wn + nf * 8 + ac;
                float* acc4 = acc[mf][nf];
                float xj0 = xxb[cg], xj1 = xxb[cg + 1];
                float2 v0, v1;
                v0.x = 2.f * acc4[0] - xi0 - xj0;
                v0.y = 2.f * acc4[1] - xi0 - xj1;
                v1.x = 2.f * acc4[2] - xi1 - xj0;
                v1.y = 2.f * acc4[3] - xi1 - xj1;
                *(float2*)(out + ((long long)b * NP + r0g) * ldo + cg) = v0;
                *(float2*)(out + ((long long)b * NP + r0g + 8) * ldo + cg) = v1;
                if (mirror) {
                    int lr0 = wm + mf * 16 + ar;           // local row
                    int lc0 = wn + nf * 8 + ac;            // local col
                    st[(lc0 + 0) * TSTR + lr0]     = v0.x;
                    st[(lc0 + 1) * TSTR + lr0]     = v0.y;
                    st[(lc0 + 0) * TSTR + lr0 + 8] = v1.x;
                    st[(lc0 + 1) * TSTR + lr0 + 8] = v1.y;
                }
            }
        }
        if (mirror) {
            __syncthreads();
            // write transposed tile: global row col0+tr, cols row0..row0+127
            for (int e = tid; e < 128 * 32; e += 256) {
                int tr = e >> 5;
                int tc = (e & 31) * 4;
                float4 val = *(float4*)&st[tr * TSTR + tc];
                *(float4*)(out + ((long long)b * NP + col0 + tr) * ldo + row0 + tc) = val;
            }
        }
    } else {
        #pragma unroll
        for (int mf = 0; mf < 4; mf++) {
            int r0g = row0 + wm + mf * 16 + ar;
            #pragma unroll
            for (int nf = 0; nf < 4; nf++) {
                int cg = col0 + wn + nf * 8 + ac;
                float* acc4 = acc[mf][nf];
                float2 v0, v1;
                v0.x = acc4[0]; v0.y = acc4[1];
                v1.x = acc4[2]; v1.y = acc4[3];
                *(float2*)(out + ((long long)b * NP + r0g) * ldo + cg) = v0;
                *(float2*)(out + ((long long)b * NP + r0g + 8) * ldo + cg) = v1;
            }
        }
    }
}

// =================== top-20 (R10-proven): sorted top-4 queues + verify ===================
__global__ void topk_kernel(const float* __restrict__ dist, int* __restrict__ idx)
{
    int row = blockIdx.x * (blockDim.x >> 5) + (threadIdx.x >> 5);
    int lane = threadIdx.x & 31;
    if (row >= NB * NP) return;
    const float* d = dist + (size_t)row * NP;
    float v[32];
    #pragma unroll
    for (int s = 0; s < 32; s++) v[s] = d[s * 32 + lane];

    float m0 = -FLT_MAX, m1 = -FLT_MAX, m2 = -FLT_MAX, m3 = -FLT_MAX;
    int q0 = 0, q1 = 0, q2 = 0, q3 = 0;
    #pragma unroll
    for (int s = 0; s < 32; s++) {
        float x = v[s];
        if (x > m3) {
            if (x > m0)      { m3 = m2; q3 = q2; m2 = m1; q2 = q1; m1 = m0; q1 = q0; m0 = x; q0 = s; }
            else if (x > m1) { m3 = m2; q3 = q2; m2 = m1; q2 = q1; m1 = x;  q1 = s; }
            else if (x > m2) { m3 = m2; q3 = q2; m2 = x;  q2 = s; }
            else             { m3 = x;  q3 = s; }
        }
    }

    float thresh = 0.f;
    #pragma unroll
    for (int t = 0; t < KNN; t++) {
        float best = m0;
        #pragma unroll
        for (int off = 16; off; off >>= 1)
            best = fmaxf(best, __shfl_xor_sync(0xffffffffu, best, off));
        unsigned mask = __ballot_sync(0xffffffffu, m0 == best);
        int wl = __ffs(mask) - 1;
        int wq = __shfl_sync(0xffffffffu, q0, wl);
        if (lane == 0) idx[row * KNN + t] = wq * 32 + wl;
        if (lane == wl) { m0 = m1; q0 = q1; m1 = m2; q1 = q2; m2 = m3; q2 = q3; m3 = -FLT_MAX; }
        thresh = best;
    }

    int cnt = 0;
    #pragma unroll
    for (int s = 0; s < 32; s++) cnt += (v[s] > thresh) ? 1 : 0;
    cnt = __reduce_add_sync(0xffffffffu, cnt);
    if (cnt == 19) return;

    // rare fallback: exact iterative selection (element = s*32 + lane)
    for (int t = 0; t < KNN; t++) {
        float best = -FLT_MAX; int bs = 0;
        #pragma unroll
        for (int s = 0; s < 32; s++)
            if (v[s] > best) { best = v[s]; bs = s; }
        int bj = bs * 32 + lane;
        #pragma unroll
        for (int off = 16; off; off >>= 1) {
            float ov = __shfl_xor_sync(0xffffffffu, best, off);
            int oj = __shfl_xor_sync(0xffffffffu, bj, off);
            if (ov > best || (ov == best && oj < bj)) { best = ov; bj = oj; }
        }
        if (lane == 0) idx[row * KNN + t] = bj;
        if ((bj & 31) == lane) {
            int ks = bj >> 5;
            #pragma unroll
            for (int s = 0; s < 32; s++)
                if (s == ks) v[s] = -FLT_MAX;
        }
    }
}

// =================== edge aggregate ===================
__global__ void aggregate_kernel(const float* __restrict__ ab, int O,
                                 const float* __restrict__ bias,
                                 const int* __restrict__ idx,
                                 float* __restrict__ out, int ldo, int ooff)
{
    int bi = blockIdx.x;
    int b = bi >> 10, i = bi & 1023;
    __shared__ int sj[KNN];
    if (threadIdx.x < KNN) sj[threadIdx.x] = idx[bi * KNN + threadIdx.x];
    __syncthreads();
    const float* abb = ab + (size_t)b * NP * 2 * O;
    for (int o = threadIdx.x; o < O; o += blockDim.x) {
        float a = abb[(size_t)i * 2 * O + o] + bias[o];
        float acc = 0.f;
        #pragma unroll
        for (int k = 0; k < KNN; k++) {
            float val = a + abb[(size_t)sj[k] * 2 * O + O + o];
            acc += fmaxf(val, 0.2f * val);
        }
        out[((size_t)b * NP + i) * ldo + ooff + o] = acc * 0.05f;
    }
}

// =================== pooling + final linear ===================
__global__ void pool_kernel(const float* __restrict__ hf, float* __restrict__ pooled)
{
    int b = blockIdx.x;
    int o = blockIdx.y * blockDim.x + threadIdx.x;
    float s = 0.f;
    for (int i = 0; i < NP; i++) s += hf[((size_t)b * NP + i) * 512 + o];
    pooled[b * 512 + o] = s * (1.f / NP);
}

__global__ void final_kernel(const float* __restrict__ pooled, const float* __restrict__ We,
                             float* __restrict__ out)
{
    int b = blockIdx.x, e = threadIdx.x;
    const float* p = pooled + b * 512;
    const float* w = We + e * 512;
    float s = 0.f;
    for (int o = 0; o < 512; o++) s += p[o] * w[o];
    out[b * 256 + e] = s;
}

// =================== host side ===================
struct LayerCfg { int C, Cp, O, coff; const float *W, *g, *be, *m, *v; };

extern "C" void kernel_launch(void* const* d_in, const int* in_sizes, int n_in,
                              void* d_out, int out_size)
{
    const float* x  = (const float*)d_in[0];
    const float* We = (const float*)d_in[21];

    float *dist, *xx, *cat, *ab, *hf, *pooled, *bias4;
    int* idx;
    __nv_bfloat16 *hl, *whl4;
    cudaGetSymbolAddress((void**)&dist,   g_dist);
    cudaGetSymbolAddress((void**)&idx,    g_idx);
    cudaGetSymbolAddress((void**)&xx,     g_xx);
    cudaGetSymbolAddress((void**)&cat,    g_cat);
    cudaGetSymbolAddress((void**)&ab,     g_ab);
    cudaGetSymbolAddress((void**)&hf,     g_hf);
    cudaGetSymbolAddress((void**)&pooled, g_pooled);
    cudaGetSymbolAddress((void**)&bias4,  g_bias4);
    cudaGetSymbolAddress((void**)&hl,     g_hl);
    cudaGetSymbolAddress((void**)&whl4,   g_whl4);

    static cudaStream_t sB = nullptr;
    static cudaEvent_t evRoot, evS[4], evB[4];
    static bool attrSet = false;
    if (!sB) {
        cudaStreamCreateWithFlags(&sB, cudaStreamNonBlocking);
        cudaEventCreateWithFlags(&evRoot, cudaEventDisableTiming);
        for (int i = 0; i < 4; i++) {
            cudaEventCreateWithFlags(&evS[i], cudaEventDisableTiming);
            cudaEventCreateWithFlags(&evB[i], cudaEventDisableTiming);
        }
    }
    if (!attrSet) {
        cudaFuncSetAttribute(mma_gemm_kernel,
                             cudaFuncAttributeMaxDynamicSharedMemorySize, GEMM_SMEM);
        attrSet = true;
    }

    LayerCfg L[4] = {
        {  3,  32,  64,   0, (const float*)d_in[1],  (const float*)d_in[2],  (const float*)d_in[3],  (const float*)d_in[4],  (const float*)d_in[5]  },
        { 64,  64, 128,   0, (const float*)d_in[6],  (const float*)d_in[7],  (const float*)d_in[8],  (const float*)d_in[9],  (const float*)d_in[10] },
        {128, 128, 256,  64, (const float*)d_in[11], (const float*)d_in[12], (const float*)d_in[13], (const float*)d_in[14], (const float*)d_in[15] },
        {448, 448, 512,   0, (const float*)d_in[16], (const float*)d_in[17], (const float*)d_in[18], (const float*)d_in[19], (const float*)d_in[20] },
    };
    int ooffs[4] = {0, 64, 192, 0};

    cudaEventRecord(evRoot, 0);
    cudaStreamWaitEvent(sB, evRoot, 0);

    for (int i = 0; i < 4; i++) {
        wfoldsplit_kernel<<<2 * L[i].O, 128, 0, sB>>>(
            L[i].W, L[i].g, L[i].be, L[i].m, L[i].v, L[i].O, L[i].C, L[i].Cp,
            whl4 + (size_t)i * 1024 * HLMAX, bias4 + i * 512);
    }

    for (int i = 0; i < 4; i++) {
        int C = L[i].C, Cp = L[i].Cp, O = L[i].O, coff = L[i].coff;
        const float* hin = (i == 0) ? x : cat;
        int ld = (i == 0) ? 3 : 448;
        float* outbuf = (i == 3) ? hf : cat;
        int ldo = (i == 3) ? 512 : 448;

        split_kernel<<<NB * NP, 128>>>(hin, ld, coff, C, (long long)NP * ld, NP,
                                       hl, Cp, xx);
        cudaEventRecord(evS[i], 0);

        cudaStreamWaitEvent(sB, evS[i], 0);
        dim3 gw((2 * O) / 128, NP / 128, NB);
        mma_gemm_kernel<<<gw, 256, GEMM_SMEM, sB>>>(
            hl, whl4 + (size_t)i * 1024 * HLMAX, Cp,
            (long long)NP * 2 * Cp, 0, nullptr, 1, ab, 2 * O);
        cudaEventRecord(evB[i], sB);

        // symmetric dist: 36 lower-triangle tiles per batch
        dim3 gd(36, 1, NB);
        mma_gemm_kernel<<<gd, 256, GEMM_SMEM>>>(
            hl, hl, Cp, (long long)NP * 2 * Cp, (long long)NP * 2 * Cp,
            xx, 0, dist, NP);
        topk_kernel<<<NB * NP / 8, 256>>>(dist, idx);

        cudaStreamWaitEvent(0, evB[i], 0);
        int bt = O < 256 ? O : 256;
        aggregate_kernel<<<NB * NP, bt>>>(ab, O, bias4 + i * 512, idx,
                                          outbuf, ldo, ooffs[i]);
    }

    pool_kernel<<<dim3(NB, 2), 256>>>(hf, pooled);
    final_kernel<<<NB, 256>>>(pooled, We, (float*)d_out);
}